// round 6
// baseline (speedup 1.0000x reference)
#include <cuda_runtime.h>
#include <cuda_bf16.h>
#include <math.h>

// Problem constants
#define Bn   32
#define Ln   36864
#define Cn   16
#define Dn   512
#define Kn   24
#define LOUT 1536
#define Mtot (Bn * LOUT)      // 49152
#define KDIM 384              // C*K reduction dim
#define SPAD 20               // smem row stride for k_offsets (conflict-free)
#define SPAD2 36              // smem row stride for BK=32 gemm (bank = 4g+cc, all distinct)

// -------- scratch (device globals) --------
__device__ unsigned g_woffT[48 * KDIM];       // tf32-converted [o][k*16+c]
__device__ unsigned g_wdefT[Dn * KDIM];       // tf32-converted [d][k*16+c]
__device__ int   g_i0[Mtot * Kn];
__device__ float g_w0[Mtot * Kn];
__device__ float g_w1[Mtot * Kn];

__device__ __forceinline__ unsigned f2tf32(float f) {
    unsigned r;
    asm("cvt.rna.tf32.f32 %0, %1;" : "=r"(r) : "f"(f));
    return r;
}
__device__ __forceinline__ unsigned sptr(const void* p) {
    return (unsigned)__cvta_generic_to_shared(p);
}

#define MMA_TF32(acc, af, bf)                                                  \
    asm volatile(                                                              \
        "mma.sync.aligned.m16n8k8.row.col.f32.tf32.tf32.f32 "                  \
        "{%0,%1,%2,%3}, {%4,%5,%6,%7}, {%8,%9}, {%0,%1,%2,%3};\n"              \
        : "+f"(acc[0]), "+f"(acc[1]), "+f"(acc[2]), "+f"(acc[3])               \
        : "r"(af[0]), "r"(af[1]), "r"(af[2]), "r"(af[3]),                      \
          "r"(bf[0]), "r"(bf[1]))

// ---------------- kernel 0: weight transpose + tf32 convert ----------------
__global__ void k_prep(const float* __restrict__ w_off, const float* __restrict__ w_def) {
    int idx = blockIdx.x * 256 + threadIdx.x;   // 48*384 + 512*384 = 215040
    if (idx < 48 * KDIM) {
        int o = idx / KDIM, i = idx - o * KDIM;
        int k = i >> 4, c = i & 15;
        g_woffT[idx] = f2tf32(w_off[(o * 16 + c) * 24 + k]);
    } else {
        int j = idx - 48 * KDIM;
        int d = j / KDIM, i = j - d * KDIM;
        int k = i >> 4, c = i & 15;
        g_wdefT[j] = f2tf32(w_def[(d * 16 + c) * 24 + k]);
    }
}

// ---------------- kernel 1: offset GEMM (tf32 TC) + metadata epilogue ------
__global__ __launch_bounds__(256) void k_offsets_tc(const float* __restrict__ x,
                                                    const float* __restrict__ b_off) {
    __shared__ unsigned sA[2][128 * SPAD];
    __shared__ unsigned sB[2][48 * SPAD];

    int tid = threadIdx.x, lane = tid & 31, wid = tid >> 5;
    int g = lane >> 2, cc = lane & 3;
    int mBase = blockIdx.x * 128;
    const float* Ax = x + (size_t)mBase * KDIM;
    int r = tid >> 1, h = tid & 1;      // A staging: row r, channels h*8..h*8+7

    float4 xa, xb2;
    auto loadA = [&](int ch) {
        const float4* p = (const float4*)(Ax + (size_t)r * KDIM + ch * 16 + h * 8);
        xa = p[0]; xb2 = p[1];
    };
    auto stsA = [&](int s) {
        unsigned* dst = &sA[s][r * SPAD + h * 8];
        uint4 q0 = make_uint4(f2tf32(xa.x),  f2tf32(xa.y),  f2tf32(xa.z),  f2tf32(xa.w));
        uint4 q1 = make_uint4(f2tf32(xb2.x), f2tf32(xb2.y), f2tf32(xb2.z), f2tf32(xb2.w));
        *(uint4*)dst = q0;
        *(uint4*)(dst + 4) = q1;
    };
    auto cpB = [&](int ch, int s) {
        if (tid < 192) {                 // 48 rows x 16 cols = 192 float4
            int row = tid >> 2, c4 = (tid & 3) * 4;
            unsigned d = sptr(&sB[s][row * SPAD + c4]);
            const unsigned* src = &g_woffT[row * KDIM + ch * 16 + c4];
            asm volatile("cp.async.cg.shared.global [%0], [%1], 16;\n" :: "r"(d), "l"(src));
        }
        asm volatile("cp.async.commit_group;\n");
    };

    float acc[6][4];
    #pragma unroll
    for (int i = 0; i < 6; i++)
        #pragma unroll
        for (int q = 0; q < 4; q++) acc[i][q] = 0.0f;

    loadA(0); cpB(0, 0); stsA(0);
    asm volatile("cp.async.wait_group 0;\n");
    __syncthreads();

    #pragma unroll 1
    for (int ch = 0; ch < 24; ch++) {
        int s = ch & 1;
        if (ch + 1 < 24) { loadA(ch + 1); cpB(ch + 1, s ^ 1); }
        const unsigned* a = &sA[s][0];
        const unsigned* b = &sB[s][0];
        #pragma unroll
        for (int ks = 0; ks < 2; ks++) {
            int kb = ks * 8;
            unsigned af[4];
            int r0 = wid * 16 + g;
            af[0] = a[r0 * SPAD + kb + cc];
            af[1] = a[(r0 + 8) * SPAD + kb + cc];
            af[2] = a[r0 * SPAD + kb + cc + 4];
            af[3] = a[(r0 + 8) * SPAD + kb + cc + 4];
            unsigned bf[6][2];
            #pragma unroll
            for (int nt = 0; nt < 6; nt++) {
                int n = nt * 8 + g;
                bf[nt][0] = b[n * SPAD + kb + cc];
                bf[nt][1] = b[n * SPAD + kb + cc + 4];
            }
            #pragma unroll
            for (int nt = 0; nt < 6; nt++) MMA_TF32(acc[nt], af, bf[nt]);
        }
        if (ch + 1 < 24) {
            stsA(s ^ 1);
            asm volatile("cp.async.wait_group 0;\n");
            __syncthreads();
        }
    }

    // epilogue: frag (c0,c1) = (dy,dx) for k=4*nt+cc at row g; (c2,c3) at row g+8
    int loBase = mBase % LOUT;
    #pragma unroll
    for (int nt = 0; nt < 6; nt++) {
        int k = 4 * nt + cc;
        float bdy = __ldg(b_off + 8 * nt + 2 * cc);
        float bdx = __ldg(b_off + 8 * nt + 2 * cc + 1);
        #pragma unroll
        for (int half = 0; half < 2; half++) {
            int rr = wid * 16 + g + half * 8;
            int m  = mBase + rr;
            int lo = loBase + rr;
            float dy = acc[nt][half * 2 + 0] + bdy;
            float dx = acc[nt][half * 2 + 1] + bdx;
            float px = (float)(lo * Kn + k) + dx;
            float wy = fmaxf(0.0f, 1.0f - fabsf(dy));
            float x0 = floorf(px);
            float lw = px - x0;
            int i0 = (int)x0;
            bool valid = (px > -1.0f) && (px < (float)Ln);
            float w0 = (valid && i0 >= 0 && i0 < Ln) ? (1.0f - lw) * wy : 0.0f;
            float w1 = (valid && (i0 + 1) >= 0 && (i0 + 1) < Ln) ? lw * wy : 0.0f;
            int idx = m * Kn + k;
            g_i0[idx] = i0;
            g_w0[idx] = w0;
            g_w1[idx] = w1;
        }
    }
}

// ---------------- kernel 2: fused sample + tf32 GEMM, BK=32 ----------------
// Each iteration covers TWO taps (32 K-cols). Thread (r=tid>>1, h=tid&1)
// stages row r, tap (2*it+h): gathers 2 x-rows x 16ch, lerps, cvt, STS.
// B streamed with cp.async. 12 iterations, double-buffered dynamic smem.
#define NIT 12
#define ASTG (128 * SPAD2)    // 4608 words per stage

__global__ __launch_bounds__(256, 2) void k_gemm_fused(const float* __restrict__ x,
                                                       const float* __restrict__ b_def,
                                                       float* __restrict__ out) {
    extern __shared__ unsigned smem[];
    unsigned* sA = smem;                  // [2][ASTG]
    unsigned* sB = smem + 2 * ASTG;       // [2][ASTG]

    int tid = threadIdx.x, lane = tid & 31, wid = tid >> 5;
    int wm = wid & 3, wn = wid >> 2;
    int g = lane >> 2, cc = lane & 3;

    int mBase = blockIdx.y * 128;
    int nBase = blockIdx.x * 128;
    int bimg = mBase / LOUT;                         // 128 | LOUT -> constant per block
    const float* xb = x + (size_t)bimg * Ln * Cn;
    const unsigned* Bg = g_wdefT + (size_t)nBase * KDIM;

    int r = tid >> 1, h = tid & 1;                   // staging row / tap-in-pair
    int m24 = (mBase + r) * Kn + h;                  // meta index base for tap 2*it+h

    int   nx_i0;  float nx_w0, nx_w1;                // prefetched meta
    float4 u0, u1, u2, u3;                           // x row a0: 16 floats
    float4 v0, v1, v2, v3;                           // x row a1: 16 floats
    float cw0, cw1;

    auto loadMeta = [&](int it) {
        int idx = m24 + it * 2;
        nx_i0 = g_i0[idx]; nx_w0 = g_w0[idx]; nx_w1 = g_w1[idx];
    };
    auto loadX = [&]() {
        int a0 = min(max(nx_i0, 0), Ln - 1);
        int a1 = min(max(nx_i0 + 1, 0), Ln - 1);
        const float4* p0 = (const float4*)(xb + (size_t)a0 * Cn);
        const float4* p1 = (const float4*)(xb + (size_t)a1 * Cn);
        u0 = p0[0]; u1 = p0[1]; u2 = p0[2]; u3 = p0[3];
        v0 = p1[0]; v1 = p1[1]; v2 = p1[2]; v3 = p1[3];
        cw0 = nx_w0; cw1 = nx_w1;
    };
    auto stsA = [&](int s) {
        unsigned* dst = &sA[s * ASTG + r * SPAD2 + h * 16];
        uint4 q;
        q.x = f2tf32(cw0 * u0.x + cw1 * v0.x);
        q.y = f2tf32(cw0 * u0.y + cw1 * v0.y);
        q.z = f2tf32(cw0 * u0.z + cw1 * v0.z);
        q.w = f2tf32(cw0 * u0.w + cw1 * v0.w);
        *(uint4*)dst = q;
        q.x = f2tf32(cw0 * u1.x + cw1 * v1.x);
        q.y = f2tf32(cw0 * u1.y + cw1 * v1.y);
        q.z = f2tf32(cw0 * u1.z + cw1 * v1.z);
        q.w = f2tf32(cw0 * u1.w + cw1 * v1.w);
        *(uint4*)(dst + 4) = q;
        q.x = f2tf32(cw0 * u2.x + cw1 * v2.x);
        q.y = f2tf32(cw0 * u2.y + cw1 * v2.y);
        q.z = f2tf32(cw0 * u2.z + cw1 * v2.z);
        q.w = f2tf32(cw0 * u2.w + cw1 * v2.w);
        *(uint4*)(dst + 8) = q;
        q.x = f2tf32(cw0 * u3.x + cw1 * v3.x);
        q.y = f2tf32(cw0 * u3.y + cw1 * v3.y);
        q.z = f2tf32(cw0 * u3.z + cw1 * v3.z);
        q.w = f2tf32(cw0 * u3.w + cw1 * v3.w);
        *(uint4*)(dst + 12) = q;
    };
    auto cpB = [&](int it, int s) {
        unsigned d = sptr(&sB[s * ASTG + r * SPAD2 + h * 16]);
        const unsigned* src = Bg + (size_t)r * KDIM + it * 32 + h * 16;
        asm volatile("cp.async.cg.shared.global [%0], [%1], 16;\n" :: "r"(d),      "l"(src));
        asm volatile("cp.async.cg.shared.global [%0], [%1], 16;\n" :: "r"(d + 16), "l"(src + 4));
        asm volatile("cp.async.cg.shared.global [%0], [%1], 16;\n" :: "r"(d + 32), "l"(src + 8));
        asm volatile("cp.async.cg.shared.global [%0], [%1], 16;\n" :: "r"(d + 48), "l"(src + 12));
        asm volatile("cp.async.commit_group;\n");
    };

    float acc[2][8][4];
    #pragma unroll
    for (int i = 0; i < 2; i++)
        #pragma unroll
        for (int j = 0; j < 8; j++)
            #pragma unroll
            for (int q = 0; q < 4; q++) acc[i][j][q] = 0.0f;

    loadMeta(0);
    loadX();
    cpB(0, 0);
    loadMeta(1);
    stsA(0);
    asm volatile("cp.async.wait_group 0;\n");
    __syncthreads();

    #pragma unroll 1
    for (int it = 0; it < NIT; it++) {
        int s = it & 1;
        if (it + 1 < NIT) {
            loadX();                     // consumes meta(it+1)
            cpB(it + 1, s ^ 1);
            if (it + 2 < NIT) loadMeta(it + 2);
        }
        const unsigned* a = &sA[s * ASTG];
        const unsigned* b = &sB[s * ASTG];
        #pragma unroll
        for (int ks = 0; ks < 4; ks++) {
            int kb = ks * 8;
            unsigned af[2][4];
            #pragma unroll
            for (int mt = 0; mt < 2; mt++) {
                int r0 = wm * 32 + mt * 16 + g;
                af[mt][0] = a[r0 * SPAD2 + kb + cc];
                af[mt][1] = a[(r0 + 8) * SPAD2 + kb + cc];
                af[mt][2] = a[r0 * SPAD2 + kb + cc + 4];
                af[mt][3] = a[(r0 + 8) * SPAD2 + kb + cc + 4];
            }
            unsigned bf[8][2];
            #pragma unroll
            for (int nt = 0; nt < 8; nt++) {
                int n = wn * 64 + nt * 8 + g;
                bf[nt][0] = b[n * SPAD2 + kb + cc];
                bf[nt][1] = b[n * SPAD2 + kb + cc + 4];
            }
            #pragma unroll
            for (int mt = 0; mt < 2; mt++)
                #pragma unroll
                for (int nt = 0; nt < 8; nt++) MMA_TF32(acc[mt][nt], af[mt], bf[nt]);
        }
        if (it + 1 < NIT) {
            stsA(s ^ 1);
            asm volatile("cp.async.wait_group 0;\n");
            __syncthreads();
        }
    }

    // epilogue
    #pragma unroll
    for (int mt = 0; mt < 2; mt++) {
        int r0 = mBase + wm * 32 + mt * 16 + g;
        #pragma unroll
        for (int nt = 0; nt < 8; nt++) {
            int col = nBase + wn * 64 + nt * 8 + 2 * cc;
            float bz0 = __ldg(b_def + col);
            float bz1 = __ldg(b_def + col + 1);
            float2 o0 = make_float2(acc[mt][nt][0] + bz0, acc[mt][nt][1] + bz1);
            float2 o1 = make_float2(acc[mt][nt][2] + bz0, acc[mt][nt][3] + bz1);
            *(float2*)(out + (size_t)r0 * Dn + col) = o0;
            *(float2*)(out + (size_t)(r0 + 8) * Dn + col) = o1;
        }
    }
}

// ---------------- launch ----------------
extern "C" void kernel_launch(void* const* d_in, const int* in_sizes, int n_in,
                              void* d_out, int out_size) {
    const float* x     = (const float*)d_in[0];
    const float* w_off = (const float*)d_in[1];
    const float* b_off = (const float*)d_in[2];
    const float* w_def = (const float*)d_in[3];
    const float* b_def = (const float*)d_in[4];
    float* out = (float*)d_out;

    (void)in_sizes; (void)n_in; (void)out_size;

    const int smemBytes = 4 * ASTG * sizeof(unsigned);   // 73728
    cudaFuncSetAttribute(k_gemm_fused, cudaFuncAttributeMaxDynamicSharedMemorySize, smemBytes);

    k_prep<<<(48 * KDIM + Dn * KDIM) / 256, 256>>>(w_off, w_def);
    k_offsets_tc<<<Mtot / 128, 256>>>(x, b_off);
    k_gemm_fused<<<dim3(Dn / 128, Mtot / 128), 256, smemBytes>>>(x, b_def, out);
}

// round 7
// speedup vs baseline: 1.1533x; 1.1533x over previous
#include <cuda_runtime.h>
#include <cuda_bf16.h>
#include <math.h>

// Problem constants
#define Bn   32
#define Ln   36864
#define Cn   16
#define Dn   512
#define Kn   24
#define LOUT 1536
#define Mtot (Bn * LOUT)      // 49152
#define KDIM 384              // C*K reduction dim
#define SPAD 20               // smem row stride (conflict-free for mma frag reads)

// -------- scratch (device globals) --------
__device__ unsigned g_woffT[48 * KDIM];          // tf32 [o][k*16+c]
__device__ unsigned g_wdefT[Dn * KDIM];          // tf32 [d][k*16+c]
__device__ unsigned g_val[(size_t)Mtot * KDIM];  // tf32 sampled values
__device__ int   g_i0[Mtot * Kn];
__device__ float g_w0[Mtot * Kn];
__device__ float g_w1[Mtot * Kn];

__device__ __forceinline__ unsigned f2tf32(float f) {
    unsigned r;
    asm("cvt.rna.tf32.f32 %0, %1;" : "=r"(r) : "f"(f));
    return r;
}
__device__ __forceinline__ unsigned sptr(const void* p) {
    return (unsigned)__cvta_generic_to_shared(p);
}

#define MMA_TF32(acc, af, bf)                                                  \
    asm volatile(                                                              \
        "mma.sync.aligned.m16n8k8.row.col.f32.tf32.tf32.f32 "                  \
        "{%0,%1,%2,%3}, {%4,%5,%6,%7}, {%8,%9}, {%0,%1,%2,%3};\n"              \
        : "+f"(acc[0]), "+f"(acc[1]), "+f"(acc[2]), "+f"(acc[3])               \
        : "r"(af[0]), "r"(af[1]), "r"(af[2]), "r"(af[3]),                      \
          "r"(bf[0]), "r"(bf[1]))

// ---------------- kernel 0: weight transpose + tf32 convert ----------------
__global__ void k_prep(const float* __restrict__ w_off, const float* __restrict__ w_def) {
    int idx = blockIdx.x * 256 + threadIdx.x;   // 48*384 + 512*384 = 215040
    if (idx < 48 * KDIM) {
        int o = idx / KDIM, i = idx - o * KDIM;
        int k = i >> 4, c = i & 15;
        g_woffT[idx] = f2tf32(w_off[(o * 16 + c) * 24 + k]);
    } else {
        int j = idx - 48 * KDIM;
        int d = j / KDIM, i = j - d * KDIM;
        int k = i >> 4, c = i & 15;
        g_wdefT[j] = f2tf32(w_def[(d * 16 + c) * 24 + k]);
    }
}

// ---------------- kernel 1: offset GEMM (tf32 TC) + metadata epilogue ------
__global__ __launch_bounds__(256) void k_offsets_tc(const float* __restrict__ x,
                                                    const float* __restrict__ b_off) {
    __shared__ unsigned sA[2][128 * SPAD];
    __shared__ unsigned sB[2][48 * SPAD];

    int tid = threadIdx.x, lane = tid & 31, wid = tid >> 5;
    int g = lane >> 2, cc = lane & 3;
    int mBase = blockIdx.x * 128;
    const float* Ax = x + (size_t)mBase * KDIM;
    int r = tid >> 1, h = tid & 1;      // A staging: row r, channels h*8..h*8+7

    float4 xa, xb2;
    auto loadA = [&](int ch) {
        const float4* p = (const float4*)(Ax + (size_t)r * KDIM + ch * 16 + h * 8);
        xa = p[0]; xb2 = p[1];
    };
    auto stsA = [&](int s) {
        unsigned* dst = &sA[s][r * SPAD + h * 8];
        uint4 q0 = make_uint4(f2tf32(xa.x),  f2tf32(xa.y),  f2tf32(xa.z),  f2tf32(xa.w));
        uint4 q1 = make_uint4(f2tf32(xb2.x), f2tf32(xb2.y), f2tf32(xb2.z), f2tf32(xb2.w));
        *(uint4*)dst = q0;
        *(uint4*)(dst + 4) = q1;
    };
    auto cpB = [&](int ch, int s) {
        if (tid < 192) {                 // 48 rows x 16 cols = 192 float4
            int row = tid >> 2, c4 = (tid & 3) * 4;
            unsigned d = sptr(&sB[s][row * SPAD + c4]);
            const unsigned* src = &g_woffT[row * KDIM + ch * 16 + c4];
            asm volatile("cp.async.cg.shared.global [%0], [%1], 16;\n" :: "r"(d), "l"(src));
        }
        asm volatile("cp.async.commit_group;\n");
    };

    float acc[6][4];
    #pragma unroll
    for (int i = 0; i < 6; i++)
        #pragma unroll
        for (int q = 0; q < 4; q++) acc[i][q] = 0.0f;

    loadA(0); cpB(0, 0); stsA(0);
    asm volatile("cp.async.wait_group 0;\n");
    __syncthreads();

    #pragma unroll 1
    for (int ch = 0; ch < 24; ch++) {
        int s = ch & 1;
        if (ch + 1 < 24) { loadA(ch + 1); cpB(ch + 1, s ^ 1); }
        const unsigned* a = &sA[s][0];
        const unsigned* b = &sB[s][0];
        #pragma unroll
        for (int ks = 0; ks < 2; ks++) {
            int kb = ks * 8;
            unsigned af[4];
            int r0 = wid * 16 + g;
            af[0] = a[r0 * SPAD + kb + cc];
            af[1] = a[(r0 + 8) * SPAD + kb + cc];
            af[2] = a[r0 * SPAD + kb + cc + 4];
            af[3] = a[(r0 + 8) * SPAD + kb + cc + 4];
            unsigned bf[6][2];
            #pragma unroll
            for (int nt = 0; nt < 6; nt++) {
                int n = nt * 8 + g;
                bf[nt][0] = b[n * SPAD + kb + cc];
                bf[nt][1] = b[n * SPAD + kb + cc + 4];
            }
            #pragma unroll
            for (int nt = 0; nt < 6; nt++) MMA_TF32(acc[nt], af, bf[nt]);
        }
        if (ch + 1 < 24) {
            stsA(s ^ 1);
            asm volatile("cp.async.wait_group 0;\n");
            __syncthreads();
        }
    }

    // epilogue: frag (c0,c1) = (dy,dx) for k=4*nt+cc at row g; (c2,c3) at row g+8
    int loBase = mBase % LOUT;
    #pragma unroll
    for (int nt = 0; nt < 6; nt++) {
        int k = 4 * nt + cc;
        float bdy = __ldg(b_off + 8 * nt + 2 * cc);
        float bdx = __ldg(b_off + 8 * nt + 2 * cc + 1);
        #pragma unroll
        for (int half = 0; half < 2; half++) {
            int rr = wid * 16 + g + half * 8;
            int m  = mBase + rr;
            int lo = loBase + rr;
            float dy = acc[nt][half * 2 + 0] + bdy;
            float dx = acc[nt][half * 2 + 1] + bdx;
            float px = (float)(lo * Kn + k) + dx;
            float wy = fmaxf(0.0f, 1.0f - fabsf(dy));
            float x0 = floorf(px);
            float lw = px - x0;
            int i0 = (int)x0;
            bool valid = (px > -1.0f) && (px < (float)Ln);
            float w0 = (valid && i0 >= 0 && i0 < Ln) ? (1.0f - lw) * wy : 0.0f;
            float w1 = (valid && (i0 + 1) >= 0 && (i0 + 1) < Ln) ? lw * wy : 0.0f;
            int idx = m * Kn + k;
            g_i0[idx] = i0;
            g_w0[idx] = w0;
            g_w1[idx] = w1;
        }
    }
}

// ---------------- kernel 2: bilinear sampling -> g_val (tf32) ----------------
__global__ void k_sample(const float* __restrict__ x) {
    int gid = blockIdx.x * 256 + threadIdx.x;
    int m = gid / KDIM;
    int rem = gid - m * KDIM;    // rem = k*16 + c
    int k = rem >> 4;
    int c = rem & 15;
    int idx = m * Kn + k;
    int i0 = g_i0[idx];
    float w0 = g_w0[idx];
    float w1 = g_w1[idx];
    int b = m / LOUT;
    int base = b * (Ln * Cn);
    int a0 = max(0, min(i0, Ln - 1));
    int a1 = max(0, min(i0 + 1, Ln - 1));
    float v0 = __ldg(x + base + a0 * Cn + c);
    float v1 = __ldg(x + base + a1 * Cn + c);
    g_val[gid] = f2tf32(w0 * v0 + w1 * v1);
}

// ---------------- kernel 3: tf32 GEMM, 3-stage cp.async pipeline ----------
// out[m][d] = val[m][:] . wdefT[d][:] + b_def[d]; A and B both pre-tf32.
#define NST 3
#define STG (128 * SPAD)      // 2560 words per operand stage

__global__ __launch_bounds__(256, 2) void k_gemm_tc(const float* __restrict__ b_def,
                                                    float* __restrict__ out) {
    extern __shared__ unsigned smem[];
    unsigned* sA = smem;                 // [NST][STG]
    unsigned* sB = smem + NST * STG;     // [NST][STG]

    int tid  = threadIdx.x;
    int lane = tid & 31;
    int wid  = tid >> 5;
    int wm = wid & 3;        // warp m tile offset wm*32
    int wn = wid >> 2;       // warp n tile offset wn*64
    int g  = lane >> 2;
    int cc = lane & 3;

    int mBase = blockIdx.y * 128;
    int nBase = blockIdx.x * 128;

    const unsigned* Ag = g_val  + (size_t)mBase * KDIM;
    const unsigned* Bg = g_wdefT + (size_t)nBase * KDIM;

    int ldRow0 = tid >> 2,         ldC0 = (tid & 3) * 4;
    int ldRow1 = (tid + 256) >> 2, ldC1 = ((tid + 256) & 3) * 4;
    int so0 = ldRow0 * SPAD + ldC0;
    int so1 = ldRow1 * SPAD + ldC1;

    auto issue = [&](int ch, int s) {
        unsigned da0 = sptr(&sA[s * STG + so0]);
        unsigned da1 = sptr(&sA[s * STG + so1]);
        unsigned db0 = sptr(&sB[s * STG + so0]);
        unsigned db1 = sptr(&sB[s * STG + so1]);
        const unsigned* a0 = Ag + (size_t)ldRow0 * KDIM + ch * 16 + ldC0;
        const unsigned* a1 = Ag + (size_t)ldRow1 * KDIM + ch * 16 + ldC1;
        const unsigned* b0 = Bg + (size_t)ldRow0 * KDIM + ch * 16 + ldC0;
        const unsigned* b1 = Bg + (size_t)ldRow1 * KDIM + ch * 16 + ldC1;
        asm volatile("cp.async.cg.shared.global [%0], [%1], 16;\n" :: "r"(da0), "l"(a0));
        asm volatile("cp.async.cg.shared.global [%0], [%1], 16;\n" :: "r"(da1), "l"(a1));
        asm volatile("cp.async.cg.shared.global [%0], [%1], 16;\n" :: "r"(db0), "l"(b0));
        asm volatile("cp.async.cg.shared.global [%0], [%1], 16;\n" :: "r"(db1), "l"(b1));
        asm volatile("cp.async.commit_group;\n");
    };

    float acc[2][8][4];
    #pragma unroll
    for (int i = 0; i < 2; i++)
        #pragma unroll
        for (int j = 0; j < 8; j++)
            #pragma unroll
            for (int q = 0; q < 4; q++) acc[i][j][q] = 0.0f;

    issue(0, 0);
    issue(1, 1);

    #pragma unroll 1
    for (int ch = 0; ch < 24; ch++) {
        int s = ch % NST;
        asm volatile("cp.async.wait_group 1;\n");   // stage ch complete
        __syncthreads();
        if (ch + 2 < 24) issue(ch + 2, (ch + 2) % NST);

        const unsigned* a = &sA[s * STG];
        const unsigned* b = &sB[s * STG];
        #pragma unroll
        for (int ks = 0; ks < 2; ks++) {
            int kb = ks * 8;
            unsigned af[2][4];
            #pragma unroll
            for (int mt = 0; mt < 2; mt++) {
                int r0 = wm * 32 + mt * 16 + g;
                af[mt][0] = a[r0 * SPAD + kb + cc];
                af[mt][1] = a[(r0 + 8) * SPAD + kb + cc];
                af[mt][2] = a[r0 * SPAD + kb + cc + 4];
                af[mt][3] = a[(r0 + 8) * SPAD + kb + cc + 4];
            }
            unsigned bf[8][2];
            #pragma unroll
            for (int nt = 0; nt < 8; nt++) {
                int n = wn * 64 + nt * 8 + g;
                bf[nt][0] = b[n * SPAD + kb + cc];
                bf[nt][1] = b[n * SPAD + kb + cc + 4];
            }
            #pragma unroll
            for (int mt = 0; mt < 2; mt++)
                #pragma unroll
                for (int nt = 0; nt < 8; nt++) MMA_TF32(acc[mt][nt], af[mt], bf[nt]);
        }
        __syncthreads();   // all warps done with stage s before it is re-filled
    }

    // epilogue
    #pragma unroll
    for (int mt = 0; mt < 2; mt++) {
        int r0 = mBase + wm * 32 + mt * 16 + g;
        #pragma unroll
        for (int nt = 0; nt < 8; nt++) {
            int col = nBase + wn * 64 + nt * 8 + 2 * cc;
            float bz0 = __ldg(b_def + col);
            float bz1 = __ldg(b_def + col + 1);
            float2 o0 = make_float2(acc[mt][nt][0] + bz0, acc[mt][nt][1] + bz1);
            float2 o1 = make_float2(acc[mt][nt][2] + bz0, acc[mt][nt][3] + bz1);
            *(float2*)(out + (size_t)r0 * Dn + col) = o0;
            *(float2*)(out + (size_t)(r0 + 8) * Dn + col) = o1;
        }
    }
}

// ---------------- launch ----------------
extern "C" void kernel_launch(void* const* d_in, const int* in_sizes, int n_in,
                              void* d_out, int out_size) {
    const float* x     = (const float*)d_in[0];
    const float* w_off = (const float*)d_in[1];
    const float* b_off = (const float*)d_in[2];
    const float* w_def = (const float*)d_in[3];
    const float* b_def = (const float*)d_in[4];
    float* out = (float*)d_out;

    (void)in_sizes; (void)n_in; (void)out_size;

    const int smemBytes = 2 * NST * STG * sizeof(unsigned);   // 61440
    cudaFuncSetAttribute(k_gemm_tc, cudaFuncAttributeMaxDynamicSharedMemorySize, smemBytes);

    k_prep<<<(48 * KDIM + Dn * KDIM) / 256, 256>>>(w_off, w_def);
    k_offsets_tc<<<Mtot / 128, 256>>>(x, b_off);
    k_sample<<<((size_t)Mtot * KDIM) / 256, 256>>>(x);
    k_gemm_tc<<<dim3(Dn / 128, Mtot / 128), 256, smemBytes>>>(b_def, out);
}

// round 15
// speedup vs baseline: 1.3875x; 1.2031x over previous
#include <cuda_runtime.h>
#include <cuda_bf16.h>
#include <math.h>

// Problem constants
#define Bn   32
#define Ln   36864
#define Cn   16
#define Dn   512
#define Kn   24
#define LOUT 1536
#define Mtot (Bn * LOUT)      // 49152
#define KDIM 384              // C*K reduction dim
#define SPAD 20               // smem row stride (conflict-free for mma frag reads)

// -------- scratch (device globals) --------
__device__ unsigned g_woffT[48 * KDIM];          // tf32 [o][k*16+c]
__device__ unsigned g_wdefT[Dn * KDIM];          // tf32 [d][k*16+c]
__device__ unsigned g_val[(size_t)Mtot * KDIM];  // tf32 sampled values
__device__ int   g_i0[Mtot * Kn];
__device__ float g_w0[Mtot * Kn];
__device__ float g_w1[Mtot * Kn];

__device__ __forceinline__ unsigned f2tf32(float f) {
    unsigned r;
    asm("cvt.rna.tf32.f32 %0, %1;" : "=r"(r) : "f"(f));
    return r;
}
__device__ __forceinline__ unsigned sptr(const void* p) {
    return (unsigned)__cvta_generic_to_shared(p);
}

#define MMA_TF32(acc, af, bf)                                                  \
    asm volatile(                                                              \
        "mma.sync.aligned.m16n8k8.row.col.f32.tf32.tf32.f32 "                  \
        "{%0,%1,%2,%3}, {%4,%5,%6,%7}, {%8,%9}, {%0,%1,%2,%3};\n"              \
        : "+f"(acc[0]), "+f"(acc[1]), "+f"(acc[2]), "+f"(acc[3])               \
        : "r"(af[0]), "r"(af[1]), "r"(af[2]), "r"(af[3]),                      \
          "r"(bf[0]), "r"(bf[1]))

// ---------------- kernel 0: weight transpose + tf32 convert ----------------
__global__ void k_prep(const float* __restrict__ w_off, const float* __restrict__ w_def) {
    int idx = blockIdx.x * 256 + threadIdx.x;   // 48*384 + 512*384 = 215040
    if (idx < 48 * KDIM) {
        int o = idx / KDIM, i = idx - o * KDIM;
        int k = i >> 4, c = i & 15;
        g_woffT[idx] = f2tf32(w_off[(o * 16 + c) * 24 + k]);
    } else {
        int j = idx - 48 * KDIM;
        int d = j / KDIM, i = j - d * KDIM;
        int k = i >> 4, c = i & 15;
        g_wdefT[j] = f2tf32(w_def[(d * 16 + c) * 24 + k]);
    }
}

// ---------------- kernel 1: offset GEMM (tf32 TC) + metadata epilogue ------
__global__ __launch_bounds__(256) void k_offsets_tc(const float* __restrict__ x,
                                                    const float* __restrict__ b_off) {
    __shared__ unsigned sA[2][128 * SPAD];
    __shared__ unsigned sB[2][48 * SPAD];

    int tid = threadIdx.x, lane = tid & 31, wid = tid >> 5;
    int g = lane >> 2, cc = lane & 3;
    int mBase = blockIdx.x * 128;
    const float* Ax = x + (size_t)mBase * KDIM;
    int r = tid >> 1, h = tid & 1;      // A staging: row r, channels h*8..h*8+7

    float4 xa, xb2;
    auto loadA = [&](int ch) {
        const float4* p = (const float4*)(Ax + (size_t)r * KDIM + ch * 16 + h * 8);
        xa = p[0]; xb2 = p[1];
    };
    auto stsA = [&](int s) {
        unsigned* dst = &sA[s][r * SPAD + h * 8];
        uint4 q0 = make_uint4(f2tf32(xa.x),  f2tf32(xa.y),  f2tf32(xa.z),  f2tf32(xa.w));
        uint4 q1 = make_uint4(f2tf32(xb2.x), f2tf32(xb2.y), f2tf32(xb2.z), f2tf32(xb2.w));
        *(uint4*)dst = q0;
        *(uint4*)(dst + 4) = q1;
    };
    auto cpB = [&](int ch, int s) {
        if (tid < 192) {                 // 48 rows x 16 cols = 192 float4
            int row = tid >> 2, c4 = (tid & 3) * 4;
            unsigned d = sptr(&sB[s][row * SPAD + c4]);
            const unsigned* src = &g_woffT[row * KDIM + ch * 16 + c4];
            asm volatile("cp.async.cg.shared.global [%0], [%1], 16;\n" :: "r"(d), "l"(src));
        }
        asm volatile("cp.async.commit_group;\n");
    };

    float acc[6][4];
    #pragma unroll
    for (int i = 0; i < 6; i++)
        #pragma unroll
        for (int q = 0; q < 4; q++) acc[i][q] = 0.0f;

    loadA(0); cpB(0, 0); stsA(0);
    asm volatile("cp.async.wait_group 0;\n");
    __syncthreads();

    #pragma unroll 1
    for (int ch = 0; ch < 24; ch++) {
        int s = ch & 1;
        if (ch + 1 < 24) { loadA(ch + 1); cpB(ch + 1, s ^ 1); }
        const unsigned* a = &sA[s][0];
        const unsigned* b = &sB[s][0];
        #pragma unroll
        for (int ks = 0; ks < 2; ks++) {
            int kb = ks * 8;
            unsigned af[4];
            int r0 = wid * 16 + g;
            af[0] = a[r0 * SPAD + kb + cc];
            af[1] = a[(r0 + 8) * SPAD + kb + cc];
            af[2] = a[r0 * SPAD + kb + cc + 4];
            af[3] = a[(r0 + 8) * SPAD + kb + cc + 4];
            unsigned bf[6][2];
            #pragma unroll
            for (int nt = 0; nt < 6; nt++) {
                int n = nt * 8 + g;
                bf[nt][0] = b[n * SPAD + kb + cc];
                bf[nt][1] = b[n * SPAD + kb + cc + 4];
            }
            #pragma unroll
            for (int nt = 0; nt < 6; nt++) MMA_TF32(acc[nt], af, bf[nt]);
        }
        if (ch + 1 < 24) {
            stsA(s ^ 1);
            asm volatile("cp.async.wait_group 0;\n");
            __syncthreads();
        }
    }

    // epilogue: frag (c0,c1) = (dy,dx) for k=4*nt+cc at row g; (c2,c3) at row g+8
    int loBase = mBase % LOUT;
    #pragma unroll
    for (int nt = 0; nt < 6; nt++) {
        int k = 4 * nt + cc;
        float bdy = __ldg(b_off + 8 * nt + 2 * cc);
        float bdx = __ldg(b_off + 8 * nt + 2 * cc + 1);
        #pragma unroll
        for (int half = 0; half < 2; half++) {
            int rr = wid * 16 + g + half * 8;
            int m  = mBase + rr;
            int lo = loBase + rr;
            float dy = acc[nt][half * 2 + 0] + bdy;
            float dx = acc[nt][half * 2 + 1] + bdx;
            float px = (float)(lo * Kn + k) + dx;
            float wy = fmaxf(0.0f, 1.0f - fabsf(dy));
            float x0 = floorf(px);
            float lw = px - x0;
            int i0 = (int)x0;
            bool valid = (px > -1.0f) && (px < (float)Ln);
            float w0 = (valid && i0 >= 0 && i0 < Ln) ? (1.0f - lw) * wy : 0.0f;
            float w1 = (valid && (i0 + 1) >= 0 && (i0 + 1) < Ln) ? lw * wy : 0.0f;
            int idx = m * Kn + k;
            g_i0[idx] = i0;
            g_w0[idx] = w0;
            g_w1[idx] = w1;
        }
    }
}

// ---------------- kernel 2: bilinear sampling -> g_val (tf32) ----------------
// One thread per (m, k) tap: meta read once, 8x LDG.128 gather, 4x STG.128 out.
__global__ __launch_bounds__(256) void k_sample(const float* __restrict__ x) {
    int t = blockIdx.x * 256 + threadIdx.x;       // Mtot*Kn = 1179648 threads
    int m = t / Kn, k = t - m * Kn;
    int i0 = g_i0[t];
    float w0 = g_w0[t];
    float w1 = g_w1[t];
    int b = m / LOUT;
    const float* xb = x + (size_t)b * Ln * Cn;
    int a0 = max(0, min(i0, Ln - 1));
    int a1 = max(0, min(i0 + 1, Ln - 1));
    const float4* p0 = (const float4*)(xb + (size_t)a0 * Cn);
    const float4* p1 = (const float4*)(xb + (size_t)a1 * Cn);
    uint4* dst = (uint4*)(g_val + (size_t)m * KDIM + k * 16);
    #pragma unroll
    for (int j = 0; j < 4; j++) {
        float4 u = p0[j];
        float4 v = p1[j];
        uint4 q;
        q.x = f2tf32(w0 * u.x + w1 * v.x);
        q.y = f2tf32(w0 * u.y + w1 * v.y);
        q.z = f2tf32(w0 * u.z + w1 * v.z);
        q.w = f2tf32(w0 * u.w + w1 * v.w);
        dst[j] = q;
    }
}

// ---------------- kernel 3: tf32 GEMM, 3-stage cp.async, 1 sync/iter ------
#define NST 3
#define STG (128 * SPAD)      // 2560 words per operand stage

__global__ __launch_bounds__(256, 2) void k_gemm_tc(const float* __restrict__ b_def,
                                                    float* __restrict__ out) {
    extern __shared__ unsigned smem[];
    unsigned* sA = smem;                 // [NST][STG]
    unsigned* sB = smem + NST * STG;     // [NST][STG]

    int tid  = threadIdx.x;
    int lane = tid & 31;
    int wid  = tid >> 5;
    int wm = wid & 3;        // warp m tile offset wm*32
    int wn = wid >> 2;       // warp n tile offset wn*64
    int g  = lane >> 2;
    int cc = lane & 3;

    int mBase = blockIdx.y * 128;
    int nBase = blockIdx.x * 128;

    const unsigned* Ag = g_val  + (size_t)mBase * KDIM;
    const unsigned* Bg = g_wdefT + (size_t)nBase * KDIM;

    int ldRow0 = tid >> 2,         ldC0 = (tid & 3) * 4;
    int ldRow1 = (tid + 256) >> 2, ldC1 = ((tid + 256) & 3) * 4;
    int so0 = ldRow0 * SPAD + ldC0;
    int so1 = ldRow1 * SPAD + ldC1;

    auto issue = [&](int ch, int s) {
        unsigned da0 = sptr(&sA[s * STG + so0]);
        unsigned da1 = sptr(&sA[s * STG + so1]);
        unsigned db0 = sptr(&sB[s * STG + so0]);
        unsigned db1 = sptr(&sB[s * STG + so1]);
        const unsigned* a0 = Ag + (size_t)ldRow0 * KDIM + ch * 16 + ldC0;
        const unsigned* a1 = Ag + (size_t)ldRow1 * KDIM + ch * 16 + ldC1;
        const unsigned* b0 = Bg + (size_t)ldRow0 * KDIM + ch * 16 + ldC0;
        const unsigned* b1 = Bg + (size_t)ldRow1 * KDIM + ch * 16 + ldC1;
        asm volatile("cp.async.cg.shared.global [%0], [%1], 16;\n" :: "r"(da0), "l"(a0));
        asm volatile("cp.async.cg.shared.global [%0], [%1], 16;\n" :: "r"(da1), "l"(a1));
        asm volatile("cp.async.cg.shared.global [%0], [%1], 16;\n" :: "r"(db0), "l"(b0));
        asm volatile("cp.async.cg.shared.global [%0], [%1], 16;\n" :: "r"(db1), "l"(b1));
        asm volatile("cp.async.commit_group;\n");
    };

    float acc[2][8][4];
    #pragma unroll
    for (int i = 0; i < 2; i++)
        #pragma unroll
        for (int j = 0; j < 8; j++)
            #pragma unroll
            for (int q = 0; q < 4; q++) acc[i][j][q] = 0.0f;

    issue(0, 0);
    issue(1, 1);

    // One barrier per iteration: a warp computing chunk ch can only read stage
    // ch%3; the fill issued this iteration targets (ch+2)%3 and last iteration's
    // fill targets (ch+1)%3 — disjoint, so no trailing barrier is needed.
    #pragma unroll 1
    for (int ch = 0; ch < 24; ch++) {
        int s = ch % NST;
        asm volatile("cp.async.wait_group 1;\n");   // stage ch complete
        __syncthreads();
        if (ch + 2 < 24) issue(ch + 2, (ch + 2) % NST);

        const unsigned* a = &sA[s * STG];
        const unsigned* b = &sB[s * STG];
        #pragma unroll
        for (int ks = 0; ks < 2; ks++) {
            int kb = ks * 8;
            unsigned af[2][4];
            #pragma unroll
            for (int mt = 0; mt < 2; mt++) {
                int r0 = wm * 32 + mt * 16 + g;
                af[mt][0] = a[r0 * SPAD + kb + cc];
                af[mt][1] = a[(r0 + 8) * SPAD + kb + cc];
                af[mt][2] = a[r0 * SPAD + kb + cc + 4];
                af[mt][3] = a[(r0 + 8) * SPAD + kb + cc + 4];
            }
            unsigned bf[8][2];
            #pragma unroll
            for (int nt = 0; nt < 8; nt++) {
                int n = wn * 64 + nt * 8 + g;
                bf[nt][0] = b[n * SPAD + kb + cc];
                bf[nt][1] = b[n * SPAD + kb + cc + 4];
            }
            #pragma unroll
            for (int mt = 0; mt < 2; mt++)
                #pragma unroll
                for (int nt = 0; nt < 8; nt++) MMA_TF32(acc[mt][nt], af[mt], bf[nt]);
        }
    }

    // epilogue
    #pragma unroll
    for (int mt = 0; mt < 2; mt++) {
        int r0 = mBase + wm * 32 + mt * 16 + g;
        #pragma unroll
        for (int nt = 0; nt < 8; nt++) {
            int col = nBase + wn * 64 + nt * 8 + 2 * cc;
            float bz0 = __ldg(b_def + col);
            float bz1 = __ldg(b_def + col + 1);
            float2 o0 = make_float2(acc[mt][nt][0] + bz0, acc[mt][nt][1] + bz1);
            float2 o1 = make_float2(acc[mt][nt][2] + bz0, acc[mt][nt][3] + bz1);
            *(float2*)(out + (size_t)r0 * Dn + col) = o0;
            *(float2*)(out + (size_t)(r0 + 8) * Dn + col) = o1;
        }
    }
}

// ---------------- launch ----------------
extern "C" void kernel_launch(void* const* d_in, const int* in_sizes, int n_in,
                              void* d_out, int out_size) {
    const float* x     = (const float*)d_in[0];
    const float* w_off = (const float*)d_in[1];
    const float* b_off = (const float*)d_in[2];
    const float* w_def = (const float*)d_in[3];
    const float* b_def = (const float*)d_in[4];
    float* out = (float*)d_out;

    (void)in_sizes; (void)n_in; (void)out_size;

    const int smemBytes = 2 * NST * STG * sizeof(unsigned);   // 61440
    cudaFuncSetAttribute(k_gemm_tc, cudaFuncAttributeMaxDynamicSharedMemorySize, smemBytes);

    k_prep<<<(48 * KDIM + Dn * KDIM) / 256, 256>>>(w_off, w_def);
    k_offsets_tc<<<Mtot / 128, 256>>>(x, b_off);
    k_sample<<<(Mtot * Kn) / 256, 256>>>(x);
    k_gemm_tc<<<dim3(Dn / 128, Mtot / 128), 256, smemBytes>>>(b_def, out);
}

// round 16
// speedup vs baseline: 1.4577x; 1.0506x over previous
#include <cuda_runtime.h>
#include <cuda_bf16.h>
#include <math.h>

// Problem constants
#define Bn   32
#define Ln   36864
#define Cn   16
#define Dn   512
#define Kn   24
#define LOUT 1536
#define Mtot (Bn * LOUT)      // 49152
#define KDIM 384              // C*K reduction dim
#define SPAD 20               // smem row stride for k_offsets (conflict-free)

// K-permutation within each 16-word group: perm(c) = (c%4)*4 + c/4 (4x4
// transpose, self-inverse). Makes each mma thread's 4 fragment words
// {cc, cc+4, cc+8, cc+12} contiguous at [4*cc .. 4*cc+3] -> LDS.128.
// g_wdefT and g_val are stored PERMUTED; g_woffT stays unpermuted.

// -------- scratch (device globals) --------
__device__ unsigned g_woffT[48 * KDIM];          // tf32 [o][k*16+c] (unpermuted)
__device__ unsigned g_wdefT[Dn * KDIM];          // tf32 [d][perm layout]
__device__ unsigned g_val[(size_t)Mtot * KDIM];  // tf32 sampled values [perm layout]
__device__ int   g_i0[Mtot * Kn];
__device__ float g_w0[Mtot * Kn];
__device__ float g_w1[Mtot * Kn];

__device__ __forceinline__ unsigned f2tf32(float f) {
    unsigned r;
    asm("cvt.rna.tf32.f32 %0, %1;" : "=r"(r) : "f"(f));
    return r;
}
__device__ __forceinline__ unsigned sptr(const void* p) {
    return (unsigned)__cvta_generic_to_shared(p);
}

#define MMA_TF32(acc, a0, a1, a2, a3, b0, b1)                                  \
    asm volatile(                                                              \
        "mma.sync.aligned.m16n8k8.row.col.f32.tf32.tf32.f32 "                  \
        "{%0,%1,%2,%3}, {%4,%5,%6,%7}, {%8,%9}, {%0,%1,%2,%3};\n"              \
        : "+f"(acc[0]), "+f"(acc[1]), "+f"(acc[2]), "+f"(acc[3])               \
        : "r"(a0), "r"(a1), "r"(a2), "r"(a3), "r"(b0), "r"(b1))

// ---------------- kernel 0: weight transpose + tf32 convert ----------------
__global__ void k_prep(const float* __restrict__ w_off, const float* __restrict__ w_def) {
    int idx = blockIdx.x * 256 + threadIdx.x;   // 48*384 + 512*384 = 215040
    if (idx < 48 * KDIM) {
        int o = idx / KDIM, i = idx - o * KDIM;
        int k = i >> 4, c = i & 15;
        g_woffT[idx] = f2tf32(w_off[(o * 16 + c) * 24 + k]);   // unpermuted
    } else {
        int j = idx - 48 * KDIM;
        int d = j / KDIM, i = j - d * KDIM;
        int k = i >> 4, c = i & 15;
        int pos = (i & ~15) | (((c & 3) << 2) | (c >> 2));     // perm(c)
        g_wdefT[d * KDIM + pos] = f2tf32(w_def[(d * 16 + c) * 24 + k]);
    }
}

// ---------------- kernel 1: offset GEMM (tf32 TC) + metadata epilogue ------
// (unchanged; reads unpermuted g_woffT)
__global__ __launch_bounds__(256) void k_offsets_tc(const float* __restrict__ x,
                                                    const float* __restrict__ b_off) {
    __shared__ unsigned sA[2][128 * SPAD];
    __shared__ unsigned sB[2][48 * SPAD];

    int tid = threadIdx.x, lane = tid & 31, wid = tid >> 5;
    int g = lane >> 2, cc = lane & 3;
    int mBase = blockIdx.x * 128;
    const float* Ax = x + (size_t)mBase * KDIM;
    int r = tid >> 1, h = tid & 1;

    float4 xa, xb2;
    auto loadA = [&](int ch) {
        const float4* p = (const float4*)(Ax + (size_t)r * KDIM + ch * 16 + h * 8);
        xa = p[0]; xb2 = p[1];
    };
    auto stsA = [&](int s) {
        unsigned* dst = &sA[s][r * SPAD + h * 8];
        uint4 q0 = make_uint4(f2tf32(xa.x),  f2tf32(xa.y),  f2tf32(xa.z),  f2tf32(xa.w));
        uint4 q1 = make_uint4(f2tf32(xb2.x), f2tf32(xb2.y), f2tf32(xb2.z), f2tf32(xb2.w));
        *(uint4*)dst = q0;
        *(uint4*)(dst + 4) = q1;
    };
    auto cpB = [&](int ch, int s) {
        if (tid < 192) {
            int row = tid >> 2, c4 = (tid & 3) * 4;
            unsigned d = sptr(&sB[s][row * SPAD + c4]);
            const unsigned* src = &g_woffT[row * KDIM + ch * 16 + c4];
            asm volatile("cp.async.cg.shared.global [%0], [%1], 16;\n" :: "r"(d), "l"(src));
        }
        asm volatile("cp.async.commit_group;\n");
    };

    float acc[6][4];
    #pragma unroll
    for (int i = 0; i < 6; i++)
        #pragma unroll
        for (int q = 0; q < 4; q++) acc[i][q] = 0.0f;

    loadA(0); cpB(0, 0); stsA(0);
    asm volatile("cp.async.wait_group 0;\n");
    __syncthreads();

    #pragma unroll 1
    for (int ch = 0; ch < 24; ch++) {
        int s = ch & 1;
        if (ch + 1 < 24) { loadA(ch + 1); cpB(ch + 1, s ^ 1); }
        const unsigned* a = &sA[s][0];
        const unsigned* b = &sB[s][0];
        #pragma unroll
        for (int ks = 0; ks < 2; ks++) {
            int kb = ks * 8;
            unsigned af[4];
            int r0 = wid * 16 + g;
            af[0] = a[r0 * SPAD + kb + cc];
            af[1] = a[(r0 + 8) * SPAD + kb + cc];
            af[2] = a[r0 * SPAD + kb + cc + 4];
            af[3] = a[(r0 + 8) * SPAD + kb + cc + 4];
            #pragma unroll
            for (int nt = 0; nt < 6; nt++) {
                int n = nt * 8 + g;
                MMA_TF32(acc[nt], af[0], af[1], af[2], af[3],
                         b[n * SPAD + kb + cc], b[n * SPAD + kb + cc + 4]);
            }
        }
        if (ch + 1 < 24) {
            stsA(s ^ 1);
            asm volatile("cp.async.wait_group 0;\n");
            __syncthreads();
        }
    }

    int loBase = mBase % LOUT;
    #pragma unroll
    for (int nt = 0; nt < 6; nt++) {
        int k = 4 * nt + cc;
        float bdy = __ldg(b_off + 8 * nt + 2 * cc);
        float bdx = __ldg(b_off + 8 * nt + 2 * cc + 1);
        #pragma unroll
        for (int half = 0; half < 2; half++) {
            int rr = wid * 16 + g + half * 8;
            int m  = mBase + rr;
            int lo = loBase + rr;
            float dy = acc[nt][half * 2 + 0] + bdy;
            float dx = acc[nt][half * 2 + 1] + bdx;
            float px = (float)(lo * Kn + k) + dx;
            float wy = fmaxf(0.0f, 1.0f - fabsf(dy));
            float x0 = floorf(px);
            float lw = px - x0;
            int i0 = (int)x0;
            bool valid = (px > -1.0f) && (px < (float)Ln);
            float w0 = (valid && i0 >= 0 && i0 < Ln) ? (1.0f - lw) * wy : 0.0f;
            float w1 = (valid && (i0 + 1) >= 0 && (i0 + 1) < Ln) ? lw * wy : 0.0f;
            int idx = m * Kn + k;
            g_i0[idx] = i0;
            g_w0[idx] = w0;
            g_w1[idx] = w1;
        }
    }
}

// ---------------- kernel 2: bilinear sampling -> g_val (tf32, PERMUTED) ----
// One thread per (m, k) tap. Transpose 4x4 in registers, still 4x STG.128.
__global__ __launch_bounds__(256) void k_sample(const float* __restrict__ x) {
    int t = blockIdx.x * 256 + threadIdx.x;       // Mtot*Kn threads
    int m = t / Kn, k = t - m * Kn;
    int i0 = g_i0[t];
    float w0 = g_w0[t];
    float w1 = g_w1[t];
    int b = m / LOUT;
    const float* xb = x + (size_t)b * Ln * Cn;
    int a0 = max(0, min(i0, Ln - 1));
    int a1 = max(0, min(i0 + 1, Ln - 1));
    const float4* p0 = (const float4*)(xb + (size_t)a0 * Cn);
    const float4* p1 = (const float4*)(xb + (size_t)a1 * Cn);
    float va[16];
    #pragma unroll
    for (int j = 0; j < 4; j++) {
        float4 u = p0[j];
        float4 v = p1[j];
        va[4 * j + 0] = w0 * u.x + w1 * v.x;
        va[4 * j + 1] = w0 * u.y + w1 * v.y;
        va[4 * j + 2] = w0 * u.z + w1 * v.z;
        va[4 * j + 3] = w0 * u.w + w1 * v.w;
    }
    uint4* dst = (uint4*)(g_val + (size_t)m * KDIM + k * 16);
    #pragma unroll
    for (int jp = 0; jp < 4; jp++) {   // dst word 4*jp+r = va[perm^-1] = va[r*4+jp]
        uint4 q;
        q.x = f2tf32(va[jp]);
        q.y = f2tf32(va[jp + 4]);
        q.z = f2tf32(va[jp + 8]);
        q.w = f2tf32(va[jp + 12]);
        dst[jp] = q;
    }
}

// ---------------- kernel 3: tf32 GEMM, 4-stage cp.async, LDS.128 frags ----
#define NST4 4
#define SP2  16                 // row stride = 16 words (no pad; phase-clean)
#define STG2 (128 * SP2)        // 2048 words = 8KB per operand stage

__global__ __launch_bounds__(256, 2) void k_gemm_tc(const float* __restrict__ b_def,
                                                    float* __restrict__ out) {
    extern __shared__ unsigned smem[];
    unsigned* sA = smem;                  // [NST4][STG2]
    unsigned* sB = smem + NST4 * STG2;    // [NST4][STG2]

    int tid  = threadIdx.x;
    int lane = tid & 31;
    int wid  = tid >> 5;
    int wm = wid & 3;        // warp m tile offset wm*32
    int wn = wid >> 2;       // warp n tile offset wn*64
    int g  = lane >> 2;
    int cc = lane & 3;

    int mBase = blockIdx.y * 128;
    int nBase = blockIdx.x * 128;

    const unsigned* Ag = g_val  + (size_t)mBase * KDIM;
    const unsigned* Bg = g_wdefT + (size_t)nBase * KDIM;

    // row = idx>>2, c4 = (idx&3)*4; smem offset row*16+c4 == 4*idx
    int ldRow0 = tid >> 2,         ldC0 = (tid & 3) * 4;
    int ldRow1 = (tid + 256) >> 2, ldC1 = ((tid + 256) & 3) * 4;
    int so0 = 4 * tid;
    int so1 = 4 * (tid + 256);

    auto issue = [&](int ch, int s) {
        unsigned da0 = sptr(&sA[s * STG2 + so0]);
        unsigned da1 = sptr(&sA[s * STG2 + so1]);
        unsigned db0 = sptr(&sB[s * STG2 + so0]);
        unsigned db1 = sptr(&sB[s * STG2 + so1]);
        const unsigned* a0 = Ag + (size_t)ldRow0 * KDIM + ch * 16 + ldC0;
        const unsigned* a1 = Ag + (size_t)ldRow1 * KDIM + ch * 16 + ldC1;
        const unsigned* b0 = Bg + (size_t)ldRow0 * KDIM + ch * 16 + ldC0;
        const unsigned* b1 = Bg + (size_t)ldRow1 * KDIM + ch * 16 + ldC1;
        asm volatile("cp.async.cg.shared.global [%0], [%1], 16;\n" :: "r"(da0), "l"(a0));
        asm volatile("cp.async.cg.shared.global [%0], [%1], 16;\n" :: "r"(da1), "l"(a1));
        asm volatile("cp.async.cg.shared.global [%0], [%1], 16;\n" :: "r"(db0), "l"(b0));
        asm volatile("cp.async.cg.shared.global [%0], [%1], 16;\n" :: "r"(db1), "l"(b1));
        asm volatile("cp.async.commit_group;\n");
    };

    float acc[2][8][4];
    #pragma unroll
    for (int i = 0; i < 2; i++)
        #pragma unroll
        for (int j = 0; j < 8; j++)
            #pragma unroll
            for (int q = 0; q < 4; q++) acc[i][j][q] = 0.0f;

    issue(0, 0);
    issue(1, 1);
    issue(2, 2);

    // Readers touch stage ch%4; in-flight fills target (ch+1..3)%4 — disjoint,
    // so a single rendezvous per iteration suffices.
    #pragma unroll 1
    for (int ch = 0; ch < 24; ch++) {
        int s = ch & 3;
        asm volatile("cp.async.wait_group 2;\n");   // stage ch complete
        __syncthreads();
        if (ch + 3 < 24) issue(ch + 3, (ch + 3) & 3);

        const unsigned* a = &sA[s * STG2];
        const unsigned* b = &sB[s * STG2];

        // A fragments: one LDS.128 per (mt, row-half) covers BOTH ks steps.
        uint4 ax[2], ay[2];
        #pragma unroll
        for (int mt = 0; mt < 2; mt++) {
            int r0 = wm * 32 + mt * 16 + g;
            ax[mt] = *(const uint4*)&a[r0 * SP2 + 4 * cc];
            ay[mt] = *(const uint4*)&a[(r0 + 8) * SP2 + 4 * cc];
        }
        // B in two halves of 4 n-tiles to bound live registers.
        #pragma unroll
        for (int nh = 0; nh < 2; nh++) {
            uint4 bz[4];
            #pragma unroll
            for (int q = 0; q < 4; q++) {
                int n = wn * 64 + (nh * 4 + q) * 8 + g;
                bz[q] = *(const uint4*)&b[n * SP2 + 4 * cc];
            }
            #pragma unroll
            for (int mt = 0; mt < 2; mt++)
                #pragma unroll
                for (int q = 0; q < 4; q++) {
                    int nt = nh * 4 + q;
                    // ks = 0 (k = cc, cc+4)
                    MMA_TF32(acc[mt][nt], ax[mt].x, ay[mt].x, ax[mt].y, ay[mt].y,
                             bz[q].x, bz[q].y);
                    // ks = 1 (k = cc+8, cc+12)
                    MMA_TF32(acc[mt][nt], ax[mt].z, ay[mt].z, ax[mt].w, ay[mt].w,
                             bz[q].z, bz[q].w);
                }
        }
    }

    // epilogue
    #pragma unroll
    for (int mt = 0; mt < 2; mt++) {
        int r0 = mBase + wm * 32 + mt * 16 + g;
        #pragma unroll
        for (int nt = 0; nt < 8; nt++) {
            int col = nBase + wn * 64 + nt * 8 + 2 * cc;
            float bz0 = __ldg(b_def + col);
            float bz1 = __ldg(b_def + col + 1);
            float2 o0 = make_float2(acc[mt][nt][0] + bz0, acc[mt][nt][1] + bz1);
            float2 o1 = make_float2(acc[mt][nt][2] + bz0, acc[mt][nt][3] + bz1);
            *(float2*)(out + (size_t)r0 * Dn + col) = o0;
            *(float2*)(out + (size_t)(r0 + 8) * Dn + col) = o1;
        }
    }
}

// ---------------- launch ----------------
extern "C" void kernel_launch(void* const* d_in, const int* in_sizes, int n_in,
                              void* d_out, int out_size) {
    const float* x     = (const float*)d_in[0];
    const float* w_off = (const float*)d_in[1];
    const float* b_off = (const float*)d_in[2];
    const float* w_def = (const float*)d_in[3];
    const float* b_def = (const float*)d_in[4];
    float* out = (float*)d_out;

    (void)in_sizes; (void)n_in; (void)out_size;

    const int smemBytes = 2 * NST4 * STG2 * sizeof(unsigned);   // 65536
    cudaFuncSetAttribute(k_gemm_tc, cudaFuncAttributeMaxDynamicSharedMemorySize, smemBytes);

    k_prep<<<(48 * KDIM + Dn * KDIM) / 256, 256>>>(w_off, w_def);
    k_offsets_tc<<<Mtot / 128, 256>>>(x, b_off);
    k_sample<<<(Mtot * Kn) / 256, 256>>>(x);
    k_gemm_tc<<<dim3(Dn / 128, Mtot / 128), 256, smemBytes>>>(b_def, out);
}